// round 3
// baseline (speedup 1.0000x reference)
#include <cuda_runtime.h>
#include <cuda_bf16.h>

// Problem constants (from reference): N=100000 nodes, E=1600000 edges, HID=64
#define MAXN 100000
#define MAXE 1600000
#define HID 64

// ---------------- scratch (no allocations allowed) ----------------
__device__ int g_is64;                               // 1 if edge_index arrived as int64
__device__ __align__(16) int   g_src[MAXE];
__device__ __align__(16) int   g_dst[MAXE];
__device__ __align__(16) float g_deg[MAXN];
__device__ __align__(16) float g_dinv[MAXN];
__device__ __align__(16) float g_norm[MAXE];
__device__ __align__(16) float g_bufA[MAXN * HID];   // xw (gather source)
__device__ __align__(16) float g_bufB[MAXN * HID];   // agg (atomic target / next GEMM input)

// ---------------- edge-index dtype detection + conversion ----------------
// If the buffer holds int64 values < 2^31, every odd 32-bit word is 0.
__global__ void detect_kernel(const int* __restrict__ ei32) {
    if (threadIdx.x == 0 && blockIdx.x == 0) {
        int allzero = 1;
        for (int i = 0; i < 64; i++)
            if (ei32[2 * i + 1] != 0) { allzero = 0; break; }
        g_is64 = allzero;
    }
}

__global__ void convert_kernel(const int* __restrict__ ei32, int e) {
    int i = blockIdx.x * blockDim.x + threadIdx.x;
    if (i >= e) return;
    if (g_is64) {
        const long long* e64 = (const long long*)ei32;
        g_src[i] = (int)e64[i];
        g_dst[i] = (int)e64[e + i];
    } else {
        g_src[i] = ei32[i];
        g_dst[i] = ei32[e + i];
    }
}

// ---------------- degree / norm precompute ----------------
__global__ void zero_deg_kernel(int n) {
    int i = blockIdx.x * blockDim.x + threadIdx.x;
    if (i < n) g_deg[i] = 0.0f;
}

__global__ void deg_kernel(int e) {
    int i = blockIdx.x * blockDim.x + threadIdx.x;
    if (i < e) atomicAdd(&g_deg[g_dst[i]], 1.0f);
}

__global__ void dinv_kernel(int n) {
    int i = blockIdx.x * blockDim.x + threadIdx.x;
    if (i < n) g_dinv[i] = rsqrtf(g_deg[i] + 1.0f);  // +1 = self loop
}

__global__ void norm_kernel(int e) {
    int i = blockIdx.x * blockDim.x + threadIdx.x;
    if (i < e) g_norm[i] = g_dinv[g_src[i]] * g_dinv[g_dst[i]];
}

// ---------------- layer 1 GEMM: x(N,3) @ W1(3,64) ----------------
// writes bufA = xw, bufB = xw * dinv^2 (self-loop init, doubles as zero-init)
__global__ void gemm_in3_kernel(const float* __restrict__ x,
                                const float* __restrict__ W1, int n) {
    int idx = blockIdx.x * blockDim.x + threadIdx.x;
    int node = idx >> 6;
    int f = idx & 63;
    if (node >= n) return;
    float x0 = x[node * 3 + 0];
    float x1 = x[node * 3 + 1];
    float x2 = x[node * 3 + 2];
    float acc = fmaf(x0, W1[f], fmaf(x1, W1[64 + f], x2 * W1[128 + f]));
    g_bufA[node * 64 + f] = acc;
    float di = g_dinv[node];
    g_bufB[node * 64 + f] = acc * di * di;
}

// ---------------- 64x64 GEMM with fused input bias+ReLU ----------------
// in = g_bufB (prev agg), applies relu(v + bias_in[f]) on load.
// out: g_bufA = h@W ; if WRITE_AGG, g_bufB = (h@W) * dinv^2 (safe in-place:
// each row is read into smem by its owning block before being overwritten).
template <bool WRITE_AGG>
__global__ __launch_bounds__(256) void gemm64_kernel(const float* __restrict__ bias_in,
                                                     const float* __restrict__ W, int n) {
    __shared__ __align__(16) float xs[4 * 64];
    int f = threadIdx.x & 63;
    int ty = threadIdx.x >> 6;  // 0..3  (node within group of 4)

    // column f of W into registers (fully unrolled -> stays in regs)
    float wcol[64];
#pragma unroll
    for (int k = 0; k < 64; k++) wcol[k] = W[k * 64 + f];

    for (int base = blockIdx.x * 4; base < n; base += gridDim.x * 4) {
        int node = base + ty;
        float v = 0.0f;
        if (node < n) v = fmaxf(g_bufB[node * 64 + f] + bias_in[f], 0.0f);
        xs[ty * 64 + f] = v;
        __syncthreads();

        float acc = 0.0f;
        const float4* xr = (const float4*)&xs[ty * 64];
#pragma unroll
        for (int k4 = 0; k4 < 16; k4++) {
            float4 xv = xr[k4];
            acc = fmaf(xv.x, wcol[4 * k4 + 0], acc);
            acc = fmaf(xv.y, wcol[4 * k4 + 1], acc);
            acc = fmaf(xv.z, wcol[4 * k4 + 2], acc);
            acc = fmaf(xv.w, wcol[4 * k4 + 3], acc);
        }
        if (node < n) {
            g_bufA[node * 64 + f] = acc;
            if (WRITE_AGG) {
                float di = g_dinv[node];
                g_bufB[node * 64 + f] = acc * di * di;
            }
        }
        __syncthreads();
    }
}

// ---------------- edge scatter: bufB[dst] += bufA[src] * norm ----------------
// 16 threads per edge, each moving one float4 via vector reduction (sm_90+).
__global__ void scatter_kernel(int e) {
    int idx = blockIdx.x * blockDim.x + threadIdx.x;
    int edge = idx >> 4;
    if (edge >= e) return;
    int c = idx & 15;
    int src = g_src[edge];
    int dst = g_dst[edge];
    float nrm = g_norm[edge];
    const float4* srow = (const float4*)&g_bufA[src * 64];
    float4 v = srow[c];
    float* dptr = &g_bufB[dst * 64 + c * 4];
    asm volatile("red.global.add.v4.f32 [%0], {%1,%2,%3,%4};"
                 :: "l"(dptr), "f"(v.x * nrm), "f"(v.y * nrm),
                    "f"(v.z * nrm), "f"(v.w * nrm)
                 : "memory");
}

// ---------------- MLP head: relu(bufA + bm1) @ Wm2 + bm2 -> sigmoid ----------------
__global__ void mlp_out_kernel(const float* __restrict__ bm1,
                               const float* __restrict__ Wm2,
                               const float* __restrict__ bm2,
                               float* __restrict__ out, int n) {
    int gtid = blockIdx.x * blockDim.x + threadIdx.x;
    int node = gtid >> 5;
    int lane = gtid & 31;
    if (node >= n) return;
    float h0 = fmaxf(g_bufA[node * 64 + lane] + bm1[lane], 0.0f);
    float h1 = fmaxf(g_bufA[node * 64 + 32 + lane] + bm1[32 + lane], 0.0f);
    float acc = fmaf(h0, Wm2[lane], h1 * Wm2[32 + lane]);
#pragma unroll
    for (int o = 16; o > 0; o >>= 1) acc += __shfl_xor_sync(0xffffffffu, acc, o);
    if (lane == 0) {
        float z = acc + bm2[0];
        out[node] = 1.0f / (1.0f + __expf(-z));
    }
}

// ---------------- launch ----------------
extern "C" void kernel_launch(void* const* d_in, const int* in_sizes, int n_in,
                              void* d_out, int out_size) {
    const float* x    = (const float*)d_in[0];
    const int*   ei32 = (const int*)d_in[1];
    const float* W1  = (const float*)d_in[2];
    const float* b1  = (const float*)d_in[3];
    const float* W2  = (const float*)d_in[4];
    const float* b2  = (const float*)d_in[5];
    const float* W3  = (const float*)d_in[6];
    const float* b3  = (const float*)d_in[7];
    const float* Wm1 = (const float*)d_in[8];
    const float* bm1 = (const float*)d_in[9];
    const float* Wm2 = (const float*)d_in[10];
    const float* bm2 = (const float*)d_in[11];
    float* out = (float*)d_out;

    int n = in_sizes[0] / 3;   // 100000
    int e = in_sizes[1] / 2;   // 1600000 (element count is 2E for either dtype)

    const int T = 256;
    int gN  = (n + T - 1) / T;
    int gE  = (e + T - 1) / T;
    int gNF = (n * 64 + T - 1) / T;
    int gSC = (e * 16 + T - 1) / T;
    int gMLP = (n * 32 + T - 1) / T;
    int gGemm = 592;  // ~4 blocks/SM target, grid-stride inside

    // edge index dtype detection + flatten to int32 src/dst
    detect_kernel<<<1, 32>>>(ei32);
    convert_kernel<<<gE, T>>>(ei32, e);

    // degree + per-edge norm (graph-invariant across layers)
    zero_deg_kernel<<<gN, T>>>(n);
    deg_kernel<<<gE, T>>>(e);
    dinv_kernel<<<gN, T>>>(n);
    norm_kernel<<<gE, T>>>(e);

    // layer 1: (x @ W1), self-loop init, edge scatter
    gemm_in3_kernel<<<gNF, T>>>(x, W1, n);
    scatter_kernel<<<gSC, T>>>(e);

    // layer 2: relu(agg1+b1) @ W2, self-loop init, scatter
    gemm64_kernel<true><<<gGemm, T>>>(b1, W2, n);
    scatter_kernel<<<gSC, T>>>(e);

    // layer 3: relu(agg2+b2) @ W3, self-loop init, scatter
    gemm64_kernel<true><<<gGemm, T>>>(b2, W3, n);
    scatter_kernel<<<gSC, T>>>(e);

    // MLP: relu(agg3+b3) @ Wm1 -> bufA ; head: relu(+bm1)@Wm2+bm2 -> sigmoid
    gemm64_kernel<false><<<gGemm, T>>>(b3, Wm1, n);
    mlp_out_kernel<<<gMLP, T>>>(bm1, Wm2, bm2, out, n);
}

// round 4
// speedup vs baseline: 1.4455x; 1.4455x over previous
#include <cuda_runtime.h>
#include <cuda_bf16.h>

// Problem constants: N=100000 nodes, E=1600000 edges, HID=64
#define MAXN 100000
#define MAXE 1600000
#define HID 64
#define NB_SCAN ((MAXN + 255) / 256)   // 391 scan blocks

// ---------------- scratch (no allocations allowed) ----------------
__device__ int g_is64;
__device__ __align__(16) int   g_src[MAXE];
__device__ __align__(16) int   g_dst[MAXE];
__device__ __align__(16) int   g_cnt[MAXN];        // in-degree (no self loop)
__device__ __align__(16) int   g_rowstart[MAXN];
__device__ __align__(16) int   g_cursor[MAXN];
__device__ __align__(16) int   g_bsum[NB_SCAN + 1];
__device__ __align__(16) int   g_csr_src[MAXE];
__device__ __align__(16) float g_csr_norm[MAXE];
__device__ __align__(16) float g_dinv[MAXN];
__device__ __align__(16) float g_bufA[MAXN * HID]; // xw (gather source)
__device__ __align__(16) float g_bufB[MAXN * HID]; // aggregated (GEMM input)

// ---------------- edge-index dtype detection (one warp) ----------------
// int64 values < 2^31 have all-zero odd 32-bit words (little-endian).
__global__ void detect_kernel(const int* __restrict__ ei32) {
    int lane = threadIdx.x;
    int v = ei32[2 * (lane * 2) + 1] | ei32[2 * (lane * 2 + 1) + 1];
    int allzero = __all_sync(0xffffffffu, v == 0);
    if (lane == 0) g_is64 = allzero;
}

__global__ void zero_cnt_kernel(int n) {
    int i = blockIdx.x * blockDim.x + threadIdx.x;
    if (i < n) g_cnt[i] = 0;
}

// convert to flat int32 src/dst + count in-degrees, one pass
__global__ void convert_count_kernel(const int* __restrict__ ei32, int e) {
    int i = blockIdx.x * blockDim.x + threadIdx.x;
    if (i >= e) return;
    int s, d;
    if (g_is64) {
        const long long* e64 = (const long long*)ei32;
        s = (int)e64[i];
        d = (int)e64[e + i];
    } else {
        s = ei32[i];
        d = ei32[e + i];
    }
    g_src[i] = s;
    g_dst[i] = d;
    atomicAdd(&g_cnt[d], 1);
}

__global__ void dinv_kernel(int n) {
    int i = blockIdx.x * blockDim.x + threadIdx.x;
    if (i < n) g_dinv[i] = rsqrtf((float)g_cnt[i] + 1.0f);  // +1 = self loop
}

// ---------------- prefix scan (3 small kernels) ----------------
__global__ void scan1_kernel(int n) {
    __shared__ int wsum[8];
    int i = blockIdx.x * 256 + threadIdx.x;
    int lane = threadIdx.x & 31, w = threadIdx.x >> 5;
    int v = (i < n) ? g_cnt[i] : 0;
    int s = v;
#pragma unroll
    for (int o = 1; o < 32; o <<= 1) {
        int t = __shfl_up_sync(0xffffffffu, s, o);
        if (lane >= o) s += t;
    }
    if (lane == 31) wsum[w] = s;
    __syncthreads();
    if (w == 0) {
        int ws = (lane < 8) ? wsum[lane] : 0;
#pragma unroll
        for (int o = 1; o < 8; o <<= 1) {
            int t = __shfl_up_sync(0xffffffffu, ws, o);
            if (lane >= o) ws += t;
        }
        if (lane < 8) wsum[lane] = ws;
    }
    __syncthreads();
    int incl = s + ((w > 0) ? wsum[w - 1] : 0);
    if (i < n) g_rowstart[i] = incl - v;   // exclusive within block
    if (threadIdx.x == 255) g_bsum[blockIdx.x] = incl;
}

__global__ void scan2_kernel(int nb) {   // single block, 512 threads
    __shared__ int wsum[16];
    int tid = threadIdx.x;
    int lane = tid & 31, w = tid >> 5;
    int v = (tid < nb) ? g_bsum[tid] : 0;
    int s = v;
#pragma unroll
    for (int o = 1; o < 32; o <<= 1) {
        int t = __shfl_up_sync(0xffffffffu, s, o);
        if (lane >= o) s += t;
    }
    if (lane == 31) wsum[w] = s;
    __syncthreads();
    if (w == 0) {
        int ws = (lane < 16) ? wsum[lane] : 0;
#pragma unroll
        for (int o = 1; o < 16; o <<= 1) {
            int t = __shfl_up_sync(0xffffffffu, ws, o);
            if (lane >= o) ws += t;
        }
        if (lane < 16) wsum[lane] = ws;
    }
    __syncthreads();
    int incl = s + ((w > 0) ? wsum[w - 1] : 0);
    if (tid < nb) g_bsum[tid] = incl - v;  // exclusive block offsets
}

__global__ void scan3_kernel(int n) {
    int i = blockIdx.x * 256 + threadIdx.x;
    if (i < n) {
        int rs = g_rowstart[i] + g_bsum[blockIdx.x];
        g_rowstart[i] = rs;
        g_cursor[i] = rs;
    }
}

// ---------------- CSR fill (src ids + norms in CSR order) ----------------
__global__ void fill_kernel(int e) {
    int i = blockIdx.x * blockDim.x + threadIdx.x;
    if (i >= e) return;
    int s = g_src[i];
    int d = g_dst[i];
    int pos = atomicAdd(&g_cursor[d], 1);
    g_csr_src[pos] = s;
    g_csr_norm[pos] = g_dinv[s] * g_dinv[d];
}

// ---------------- layer 1 GEMM: x(N,3) @ W1(3,64) -> bufA ----------------
__global__ void gemm_in3_kernel(const float* __restrict__ x,
                                const float* __restrict__ W1, int n) {
    int idx = blockIdx.x * blockDim.x + threadIdx.x;
    int node = idx >> 6;
    int f = idx & 63;
    if (node >= n) return;
    float x0 = x[node * 3 + 0];
    float x1 = x[node * 3 + 1];
    float x2 = x[node * 3 + 2];
    g_bufA[node * 64 + f] = fmaf(x0, W1[f], fmaf(x1, W1[64 + f], x2 * W1[128 + f]));
}

// ---------------- CSR gather: bufB[d] = sum_{s in N(d)} bufA[s]*norm + self ----
// 16 threads per node; lane c owns features [4c, 4c+4).
__global__ __launch_bounds__(256) void gather_kernel(int n) {
    int idx = blockIdx.x * blockDim.x + threadIdx.x;
    int node = idx >> 4;
    int c = idx & 15;
    if (node >= n) return;
    int beg = g_rowstart[node];
    int cnt = g_cnt[node];
    const float4* __restrict__ A = (const float4*)g_bufA;
    float di = g_dinv[node];
    float s2 = di * di;
    float4 self = A[node * 16 + c];
    float4 acc = make_float4(self.x * s2, self.y * s2, self.z * s2, self.w * s2);
    int j = 0;
    for (; j + 1 < cnt; j += 2) {
        int s0 = __ldg(&g_csr_src[beg + j]);
        int s1 = __ldg(&g_csr_src[beg + j + 1]);
        float n0 = __ldg(&g_csr_norm[beg + j]);
        float n1 = __ldg(&g_csr_norm[beg + j + 1]);
        float4 v0 = A[s0 * 16 + c];
        float4 v1 = A[s1 * 16 + c];
        acc.x = fmaf(v0.x, n0, acc.x); acc.y = fmaf(v0.y, n0, acc.y);
        acc.z = fmaf(v0.z, n0, acc.z); acc.w = fmaf(v0.w, n0, acc.w);
        acc.x = fmaf(v1.x, n1, acc.x); acc.y = fmaf(v1.y, n1, acc.y);
        acc.z = fmaf(v1.z, n1, acc.z); acc.w = fmaf(v1.w, n1, acc.w);
    }
    if (j < cnt) {
        int s0 = __ldg(&g_csr_src[beg + j]);
        float n0 = __ldg(&g_csr_norm[beg + j]);
        float4 v0 = A[s0 * 16 + c];
        acc.x = fmaf(v0.x, n0, acc.x); acc.y = fmaf(v0.y, n0, acc.y);
        acc.z = fmaf(v0.z, n0, acc.z); acc.w = fmaf(v0.w, n0, acc.w);
    }
    ((float4*)g_bufB)[node * 16 + c] = acc;
}

// ---------------- 64x64 GEMM, fused input bias+ReLU: bufB -> bufA ----------
__global__ __launch_bounds__(256) void gemm64_kernel(const float* __restrict__ bias_in,
                                                     const float* __restrict__ W, int n) {
    __shared__ __align__(16) float xs[4 * 64];
    int f = threadIdx.x & 63;
    int ty = threadIdx.x >> 6;

    float wcol[64];
#pragma unroll
    for (int k = 0; k < 64; k++) wcol[k] = W[k * 64 + f];

    for (int base = blockIdx.x * 4; base < n; base += gridDim.x * 4) {
        int node = base + ty;
        float v = 0.0f;
        if (node < n) v = fmaxf(g_bufB[node * 64 + f] + bias_in[f], 0.0f);
        xs[ty * 64 + f] = v;
        __syncthreads();

        float acc = 0.0f;
        const float4* xr = (const float4*)&xs[ty * 64];
#pragma unroll
        for (int k4 = 0; k4 < 16; k4++) {
            float4 xv = xr[k4];
            acc = fmaf(xv.x, wcol[4 * k4 + 0], acc);
            acc = fmaf(xv.y, wcol[4 * k4 + 1], acc);
            acc = fmaf(xv.z, wcol[4 * k4 + 2], acc);
            acc = fmaf(xv.w, wcol[4 * k4 + 3], acc);
        }
        if (node < n) g_bufA[node * 64 + f] = acc;
        __syncthreads();
    }
}

// ---------------- MLP head: relu(bufA + bm1) @ Wm2 + bm2 -> sigmoid --------
__global__ void mlp_out_kernel(const float* __restrict__ bm1,
                               const float* __restrict__ Wm2,
                               const float* __restrict__ bm2,
                               float* __restrict__ out, int n) {
    int gtid = blockIdx.x * blockDim.x + threadIdx.x;
    int node = gtid >> 5;
    int lane = gtid & 31;
    if (node >= n) return;
    float h0 = fmaxf(g_bufA[node * 64 + lane] + bm1[lane], 0.0f);
    float h1 = fmaxf(g_bufA[node * 64 + 32 + lane] + bm1[32 + lane], 0.0f);
    float acc = fmaf(h0, Wm2[lane], h1 * Wm2[32 + lane]);
#pragma unroll
    for (int o = 16; o > 0; o >>= 1) acc += __shfl_xor_sync(0xffffffffu, acc, o);
    if (lane == 0) {
        float z = acc + bm2[0];
        out[node] = 1.0f / (1.0f + __expf(-z));
    }
}

// ---------------- launch ----------------
extern "C" void kernel_launch(void* const* d_in, const int* in_sizes, int n_in,
                              void* d_out, int out_size) {
    const float* x    = (const float*)d_in[0];
    const int*   ei32 = (const int*)d_in[1];
    const float* W1  = (const float*)d_in[2];
    const float* b1  = (const float*)d_in[3];
    const float* W2  = (const float*)d_in[4];
    const float* b2  = (const float*)d_in[5];
    const float* W3  = (const float*)d_in[6];
    const float* b3  = (const float*)d_in[7];
    const float* Wm1 = (const float*)d_in[8];
    const float* bm1 = (const float*)d_in[9];
    const float* Wm2 = (const float*)d_in[10];
    const float* bm2 = (const float*)d_in[11];
    float* out = (float*)d_out;

    int n = in_sizes[0] / 3;   // 100000
    int e = in_sizes[1] / 2;   // 1600000

    const int T = 256;
    int gN   = (n + T - 1) / T;
    int gE   = (e + T - 1) / T;
    int gNF  = (n * 64 + T - 1) / T;
    int gGA  = (n * 16 + T - 1) / T;
    int gMLP = (n * 32 + T - 1) / T;
    int gGemm = 592;
    int nb = gN;  // scan blocks (256 elems each)

    // ---- CSR build (once per replay, amortized over 3 layers) ----
    detect_kernel<<<1, 32>>>(ei32);
    zero_cnt_kernel<<<gN, T>>>(n);
    convert_count_kernel<<<gE, T>>>(ei32, e);
    dinv_kernel<<<gN, T>>>(n);
    scan1_kernel<<<nb, 256>>>(n);
    scan2_kernel<<<1, 512>>>(nb);
    scan3_kernel<<<nb, 256>>>(n);
    fill_kernel<<<gE, T>>>(e);

    // ---- layer 1 ----
    gemm_in3_kernel<<<gNF, T>>>(x, W1, n);
    gather_kernel<<<gGA, T>>>(n);
    // ---- layer 2 ----
    gemm64_kernel<<<gGemm, T>>>(b1, W2, n);
    gather_kernel<<<gGA, T>>>(n);
    // ---- layer 3 ----
    gemm64_kernel<<<gGemm, T>>>(b2, W3, n);
    gather_kernel<<<gGA, T>>>(n);
    // ---- MLP head ----
    gemm64_kernel<<<gGemm, T>>>(b3, Wm1, n);
    mlp_out_kernel<<<gMLP, T>>>(bm1, Wm2, bm2, out, n);
}

// round 5
// speedup vs baseline: 1.6128x; 1.1157x over previous
#include <cuda_runtime.h>
#include <cuda_fp16.h>

// Problem constants: N=100000 nodes, E=1600000 edges, HID=64
#define MAXN 100000
#define MAXE 1600000
#define HID 64
#define NB_SCAN ((MAXN + 255) / 256)   // 391 scan blocks

// ---------------- scratch (no allocations allowed) ----------------
__device__ int g_is64;
__device__ __align__(16) int    g_cnt[MAXN];        // in-degree (no self loop)
__device__ __align__(16) int    g_rowstart[MAXN];
__device__ __align__(16) int    g_cursor[MAXN];
__device__ __align__(16) int    g_bsum[NB_SCAN + 1];
__device__ __align__(16) int2   g_csr[MAXE];        // {src, norm-as-int-bits}
__device__ __align__(16) float  g_dinv[MAXN];
__device__ __align__(16) __half g_bufA[MAXN * HID]; // features (gather source, fp16)
__device__ __align__(16) float  g_bufB[MAXN * HID]; // aggregated (GEMM input, fp32)

// ---------------- edge-index dtype detection (one warp) ----------------
// int64 values < 2^31 have all-zero odd 32-bit words (little-endian).
__global__ void detect_kernel(const int* __restrict__ ei32) {
    int lane = threadIdx.x;
    int v = ei32[2 * (lane * 2) + 1] | ei32[2 * (lane * 2 + 1) + 1];
    int allzero = __all_sync(0xffffffffu, v == 0);
    if (lane == 0) g_is64 = allzero;
}

__global__ void zero_cnt_kernel(int n) {
    int i = blockIdx.x * blockDim.x + threadIdx.x;
    if (i < n) g_cnt[i] = 0;
}

// count in-degrees reading edge buffer directly
__global__ void count_kernel(const int* __restrict__ ei32, int e) {
    int i = blockIdx.x * blockDim.x + threadIdx.x;
    if (i >= e) return;
    int d;
    if (g_is64) d = (int)((const long long*)ei32)[e + i];
    else        d = ei32[e + i];
    atomicAdd(&g_cnt[d], 1);
}

// ---------------- prefix scan (dinv fused into pass 1) ----------------
__global__ void scan1_kernel(int n) {
    __shared__ int wsum[8];
    int i = blockIdx.x * 256 + threadIdx.x;
    int lane = threadIdx.x & 31, w = threadIdx.x >> 5;
    int v = (i < n) ? g_cnt[i] : 0;
    if (i < n) g_dinv[i] = rsqrtf((float)v + 1.0f);  // +1 = self loop
    int s = v;
#pragma unroll
    for (int o = 1; o < 32; o <<= 1) {
        int t = __shfl_up_sync(0xffffffffu, s, o);
        if (lane >= o) s += t;
    }
    if (lane == 31) wsum[w] = s;
    __syncthreads();
    if (w == 0) {
        int ws = (lane < 8) ? wsum[lane] : 0;
#pragma unroll
        for (int o = 1; o < 8; o <<= 1) {
            int t = __shfl_up_sync(0xffffffffu, ws, o);
            if (lane >= o) ws += t;
        }
        if (lane < 8) wsum[lane] = ws;
    }
    __syncthreads();
    int incl = s + ((w > 0) ? wsum[w - 1] : 0);
    if (i < n) g_rowstart[i] = incl - v;   // exclusive within block
    if (threadIdx.x == 255) g_bsum[blockIdx.x] = incl;
}

__global__ void scan2_kernel(int nb) {   // single block, 512 threads
    __shared__ int wsum[16];
    int tid = threadIdx.x;
    int lane = tid & 31, w = tid >> 5;
    int v = (tid < nb) ? g_bsum[tid] : 0;
    int s = v;
#pragma unroll
    for (int o = 1; o < 32; o <<= 1) {
        int t = __shfl_up_sync(0xffffffffu, s, o);
        if (lane >= o) s += t;
    }
    if (lane == 31) wsum[w] = s;
    __syncthreads();
    if (w == 0) {
        int ws = (lane < 16) ? wsum[lane] : 0;
#pragma unroll
        for (int o = 1; o < 16; o <<= 1) {
            int t = __shfl_up_sync(0xffffffffu, ws, o);
            if (lane >= o) ws += t;
        }
        if (lane < 16) wsum[lane] = ws;
    }
    __syncthreads();
    int incl = s + ((w > 0) ? wsum[w - 1] : 0);
    if (tid < nb) g_bsum[tid] = incl - v;  // exclusive block offsets
}

__global__ void scan3_kernel(int n) {
    int i = blockIdx.x * 256 + threadIdx.x;
    if (i < n) {
        int rs = g_rowstart[i] + g_bsum[blockIdx.x];
        g_rowstart[i] = rs;
        g_cursor[i] = rs;
    }
}

// ---------------- CSR fill: packed {src, norm} in CSR order ----------------
__global__ void fill_kernel(const int* __restrict__ ei32, int e) {
    int i = blockIdx.x * blockDim.x + threadIdx.x;
    if (i >= e) return;
    int s, d;
    if (g_is64) {
        const long long* e64 = (const long long*)ei32;
        s = (int)e64[i];
        d = (int)e64[e + i];
    } else {
        s = ei32[i];
        d = ei32[e + i];
    }
    int pos = atomicAdd(&g_cursor[d], 1);
    float nrm = g_dinv[s] * g_dinv[d];
    g_csr[pos] = make_int2(s, __float_as_int(nrm));
}

// ---------------- layer 1 GEMM: x(N,3) @ W1(3,64) -> bufA (fp16) ----------
__global__ void gemm_in3_kernel(const float* __restrict__ x,
                                const float* __restrict__ W1, int n) {
    int idx = blockIdx.x * blockDim.x + threadIdx.x;
    int node = idx >> 6;
    int f = idx & 63;
    if (node >= n) return;
    float x0 = x[node * 3 + 0];
    float x1 = x[node * 3 + 1];
    float x2 = x[node * 3 + 2];
    float acc = fmaf(x0, W1[f], fmaf(x1, W1[64 + f], x2 * W1[128 + f]));
    g_bufA[node * 64 + f] = __float2half_rn(acc);
}

// ---------------- CSR gather: bufB[d] = sum bufA[s]*norm + self (fp32 acc) ----
// 16 threads per node; lane c owns features [4c, 4c+4) (4 halves = 8B/lane).
__global__ __launch_bounds__(256) void gather_kernel(int n) {
    int idx = blockIdx.x * blockDim.x + threadIdx.x;
    int node = idx >> 4;
    int c = idx & 15;
    if (node >= n) return;
    int beg = g_rowstart[node];
    int cnt = g_cnt[node];
    const uint2* __restrict__ A = (const uint2*)g_bufA;  // row = 16 uint2
    float di = g_dinv[node];
    float s2 = di * di;

    uint2 sv = A[node * 16 + c];
    float2 a0 = __half22float2(*(const __half2*)&sv.x);
    float2 a1 = __half22float2(*(const __half2*)&sv.y);
    float4 acc = make_float4(a0.x * s2, a0.y * s2, a1.x * s2, a1.y * s2);

    int j = 0;
    for (; j + 1 < cnt; j += 2) {
        int2 e0 = __ldg(&g_csr[beg + j]);
        int2 e1 = __ldg(&g_csr[beg + j + 1]);
        uint2 v0 = __ldg(&A[e0.x * 16 + c]);
        uint2 v1 = __ldg(&A[e1.x * 16 + c]);
        float n0 = __int_as_float(e0.y);
        float n1 = __int_as_float(e1.y);
        float2 p0 = __half22float2(*(const __half2*)&v0.x);
        float2 p1 = __half22float2(*(const __half2*)&v0.y);
        acc.x = fmaf(p0.x, n0, acc.x); acc.y = fmaf(p0.y, n0, acc.y);
        acc.z = fmaf(p1.x, n0, acc.z); acc.w = fmaf(p1.y, n0, acc.w);
        float2 q0 = __half22float2(*(const __half2*)&v1.x);
        float2 q1 = __half22float2(*(const __half2*)&v1.y);
        acc.x = fmaf(q0.x, n1, acc.x); acc.y = fmaf(q0.y, n1, acc.y);
        acc.z = fmaf(q1.x, n1, acc.z); acc.w = fmaf(q1.y, n1, acc.w);
    }
    if (j < cnt) {
        int2 e0 = __ldg(&g_csr[beg + j]);
        uint2 v0 = __ldg(&A[e0.x * 16 + c]);
        float n0 = __int_as_float(e0.y);
        float2 p0 = __half22float2(*(const __half2*)&v0.x);
        float2 p1 = __half22float2(*(const __half2*)&v0.y);
        acc.x = fmaf(p0.x, n0, acc.x); acc.y = fmaf(p0.y, n0, acc.y);
        acc.z = fmaf(p1.x, n0, acc.z); acc.w = fmaf(p1.y, n0, acc.w);
    }
    ((float4*)g_bufB)[node * 16 + c] = acc;
}

// ---------------- 64x64 GEMM, fused input bias+ReLU: bufB(f32) -> bufA(f16) --
__global__ __launch_bounds__(256) void gemm64_kernel(const float* __restrict__ bias_in,
                                                     const float* __restrict__ W, int n) {
    __shared__ __align__(16) float xs[4 * 64];
    int f = threadIdx.x & 63;
    int ty = threadIdx.x >> 6;

    float wcol[64];
#pragma unroll
    for (int k = 0; k < 64; k++) wcol[k] = W[k * 64 + f];

    for (int base = blockIdx.x * 4; base < n; base += gridDim.x * 4) {
        int node = base + ty;
        float v = 0.0f;
        if (node < n) v = fmaxf(g_bufB[node * 64 + f] + bias_in[f], 0.0f);
        xs[ty * 64 + f] = v;
        __syncthreads();

        float acc = 0.0f;
        const float4* xr = (const float4*)&xs[ty * 64];
#pragma unroll
        for (int k4 = 0; k4 < 16; k4++) {
            float4 xv = xr[k4];
            acc = fmaf(xv.x, wcol[4 * k4 + 0], acc);
            acc = fmaf(xv.y, wcol[4 * k4 + 1], acc);
            acc = fmaf(xv.z, wcol[4 * k4 + 2], acc);
            acc = fmaf(xv.w, wcol[4 * k4 + 3], acc);
        }
        if (node < n) g_bufA[node * 64 + f] = __float2half_rn(acc);
        __syncthreads();
    }
}

// ---------------- MLP head: relu(bufA + bm1) @ Wm2 + bm2 -> sigmoid --------
__global__ void mlp_out_kernel(const float* __restrict__ bm1,
                               const float* __restrict__ Wm2,
                               const float* __restrict__ bm2,
                               float* __restrict__ out, int n) {
    int gtid = blockIdx.x * blockDim.x + threadIdx.x;
    int node = gtid >> 5;
    int lane = gtid & 31;
    if (node >= n) return;
    float h0 = fmaxf(__half2float(g_bufA[node * 64 + lane]) + bm1[lane], 0.0f);
    float h1 = fmaxf(__half2float(g_bufA[node * 64 + 32 + lane]) + bm1[32 + lane], 0.0f);
    float acc = fmaf(h0, Wm2[lane], h1 * Wm2[32 + lane]);
#pragma unroll
    for (int o = 16; o > 0; o >>= 1) acc += __shfl_xor_sync(0xffffffffu, acc, o);
    if (lane == 0) {
        float z = acc + bm2[0];
        out[node] = 1.0f / (1.0f + __expf(-z));
    }
}

// ---------------- launch ----------------
extern "C" void kernel_launch(void* const* d_in, const int* in_sizes, int n_in,
                              void* d_out, int out_size) {
    const float* x    = (const float*)d_in[0];
    const int*   ei32 = (const int*)d_in[1];
    const float* W1  = (const float*)d_in[2];
    const float* b1  = (const float*)d_in[3];
    const float* W2  = (const float*)d_in[4];
    const float* b2  = (const float*)d_in[5];
    const float* W3  = (const float*)d_in[6];
    const float* b3  = (const float*)d_in[7];
    const float* Wm1 = (const float*)d_in[8];
    const float* bm1 = (const float*)d_in[9];
    const float* Wm2 = (const float*)d_in[10];
    const float* bm2 = (const float*)d_in[11];
    float* out = (float*)d_out;

    int n = in_sizes[0] / 3;   // 100000
    int e = in_sizes[1] / 2;   // 1600000

    const int T = 256;
    int gN   = (n + T - 1) / T;
    int gE   = (e + T - 1) / T;
    int gNF  = (n * 64 + T - 1) / T;
    int gGA  = (n * 16 + T - 1) / T;
    int gMLP = (n * 32 + T - 1) / T;
    int gGemm = 592;
    int nb = gN;  // scan blocks

    // ---- CSR build ----
    detect_kernel<<<1, 32>>>(ei32);
    zero_cnt_kernel<<<gN, T>>>(n);
    count_kernel<<<gE, T>>>(ei32, e);
    scan1_kernel<<<nb, 256>>>(n);      // also writes dinv
    scan2_kernel<<<1, 512>>>(nb);
    scan3_kernel<<<nb, 256>>>(n);
    fill_kernel<<<gE, T>>>(ei32, e);

    // ---- layer 1 ----
    gemm_in3_kernel<<<gNF, T>>>(x, W1, n);
    gather_kernel<<<gGA, T>>>(n);
    // ---- layer 2 ----
    gemm64_kernel<<<gGemm, T>>>(b1, W2, n);
    gather_kernel<<<gGA, T>>>(n);
    // ---- layer 3 ----
    gemm64_kernel<<<gGemm, T>>>(b2, W3, n);
    gather_kernel<<<gGA, T>>>(n);
    // ---- MLP head ----
    gemm64_kernel<<<gGemm, T>>>(b3, Wm1, n);
    mlp_out_kernel<<<gMLP, T>>>(bm1, Wm2, bm2, out, n);
}